// round 2
// baseline (speedup 1.0000x reference)
#include <cuda_runtime.h>

#define B_TOTAL   16384
#define T_STEPS   40
#define UNITS     256
#define GATES     1024          // 4*UNITS, gate order i,f,g,o
#define VOCAB     128
#define BM        128           // batch rows per block
#define GRID      (B_TOTAL / BM)   // 128
#define NTHREADS  512
#define HT_STRIDE 130           // 128 rows + 2 pad (even, keeps 8B alignment)

typedef unsigned long long u64;

// Scratch (allocation-free rule: static __device__ arrays)
__device__ float g_c[B_TOTAL * UNITS];
__device__ float g_h[B_TOTAL * UNITS];

__device__ __forceinline__ u64 pack2(float lo, float hi) {
    u64 r; asm("mov.b64 %0, {%1, %2};" : "=l"(r) : "f"(lo), "f"(hi)); return r;
}
__device__ __forceinline__ void ffma2(u64 &d, u64 a, u64 b) {
    asm("fma.rn.f32x2 %0, %1, %2, %3;" : "=l"(d) : "l"(a), "l"(b), "l"(d));
}
__device__ __forceinline__ float lo32(u64 v){ return __uint_as_float((unsigned)(v & 0xffffffffull)); }
__device__ __forceinline__ float hi32(u64 v){ return __uint_as_float((unsigned)(v >> 32)); }

// exp-based activations: ~1e-6 rel err, 2 MUFU each; saturate correctly at +-inf
__device__ __forceinline__ float sigm(float x){
    float t = __expf(-x);
    return __fdividef(1.0f, 1.0f + t);
}
__device__ __forceinline__ float tanh_f(float x){
    float t = __expf(2.0f * x);              // x->-inf: t=0 -> -1 ; x->+inf: t=inf -> 1
    return 1.0f - __fdividef(2.0f, 1.0f + t);
}

// Shared layout (dynamic): hT[256][130] | Wsh[128][128] | chars[128][40]
#define SMEM_FLOATS (UNITS*HT_STRIDE + 128*128)
#define SMEM_BYTES  ((SMEM_FLOATS + BM*T_STEPS) * 4)   // 219,136 B

__global__ void __launch_bounds__(NTHREADS, 1)
lstm_persist_kernel(const int*   __restrict__ inputs,   // [16384,40]
                    const float* __restrict__ W_ih,     // [128,1024]
                    const float* __restrict__ W_hh,     // [256,1024]
                    const float* __restrict__ bias,     // [1024]
                    const float* __restrict__ W_out,    // [256,128]
                    const float* __restrict__ b_out,    // [128]
                    float*       __restrict__ out)      // [16384,128]
{
    extern __shared__ float smem[];
    float* hT    = smem;                              // [256][130]  h transposed: hT[k][row]
    float* Wsh   = smem + UNITS * HT_STRIDE;          // [128][128]  staged W_hh slice
    int*   chars = (int*)(Wsh + 128 * 128);           // [128][40]

    const int tid = threadIdx.x;
    const int tu  = tid & 31;      // unit lane within chunk
    const int tb  = tid >> 5;      // row group 0..15 (8 rows each)
    const int b0  = blockIdx.x * BM;

    // ---- init: h0 = 0, c0 = 0, stage chars ----
    for (int i = tid; i < UNITS * HT_STRIDE; i += NTHREADS) hT[i] = 0.0f;
    for (int i = tid; i < BM * UNITS;        i += NTHREADS) g_c[b0 * UNITS + i] = 0.0f;
    for (int i = tid; i < BM * T_STEPS;      i += NTHREADS) chars[i] = inputs[b0 * T_STEPS + i];
    __syncthreads();

    // ================= time loop =================
    for (int t = 0; t < T_STEPS; ++t) {
        // unit-chunks of 32: each lane tu owns unit u = 32*uc + tu (all 4 gates)
        for (int uc = 0; uc < 8; ++uc) {
            const int u = (uc << 5) + tu;
            u64 acc[4][4];                 // [rowpair][gate] packed f32x2 (rows 2rp, 2rp+1)
            #pragma unroll
            for (int rp = 0; rp < 4; ++rp)
                #pragma unroll
                for (int g = 0; g < 4; ++g) acc[rp][g] = 0ULL;

            #pragma unroll
            for (int kh = 0; kh < 2; ++kh) {        // K halves of 128
                __syncthreads();
                // stage W_hh[kh*128 .. +128][cols for this unit chunk] -> Wsh[kk][g*32+uu]
                #pragma unroll
                for (int j = 0; j < 8; ++j) {
                    int q  = tid + NTHREADS * j;    // 0..4095
                    int kk = q >> 5;
                    int cq = q & 31;
                    int g  = cq >> 3;
                    int f4 = (cq & 7) << 2;
                    float4 v = *reinterpret_cast<const float4*>(
                        W_hh + (kh * 128 + kk) * GATES + g * UNITS + (uc << 5) + f4);
                    *reinterpret_cast<float4*>(&Wsh[kk * 128 + (g << 5) + f4]) = v;
                }
                __syncthreads();

                const float* hbase = hT + (kh * 128) * HT_STRIDE + (tb << 3);
                const float* wbase = Wsh + tu;
                #pragma unroll 4
                for (int kk = 0; kk < 128; ++kk) {
                    const float* hrow = hbase + kk * HT_STRIDE;
                    u64 h0 = *reinterpret_cast<const u64*>(hrow + 0);   // rows 0,1 of group
                    u64 h1 = *reinterpret_cast<const u64*>(hrow + 2);
                    u64 h2 = *reinterpret_cast<const u64*>(hrow + 4);
                    u64 h3 = *reinterpret_cast<const u64*>(hrow + 6);
                    const float* wrow = wbase + kk * 128;
                    #pragma unroll
                    for (int g = 0; g < 4; ++g) {
                        float w = wrow[g << 5];
                        u64 wd = pack2(w, w);
                        ffma2(acc[0][g], h0, wd);
                        ffma2(acc[1][g], h1, wd);
                        ffma2(acc[2][g], h2, wd);
                        ffma2(acc[3][g], h3, wd);
                    }
                }
            }

            // ---- epilogue: gates + state update (z = acc + xz + b) ----
            float bb[4];
            #pragma unroll
            for (int g = 0; g < 4; ++g) bb[g] = bias[g * UNITS + u];

            #pragma unroll
            for (int rp = 0; rp < 4; ++rp) {
                #pragma unroll
                for (int half = 0; half < 2; ++half) {
                    int r  = (tb << 3) + (rp << 1) + half;
                    int bg = b0 + r;
                    int ch = chars[r * T_STEPS + t];
                    const float* xrow = W_ih + ch * GATES + u;
                    float a0 = half ? hi32(acc[rp][0]) : lo32(acc[rp][0]);
                    float a1 = half ? hi32(acc[rp][1]) : lo32(acc[rp][1]);
                    float a2 = half ? hi32(acc[rp][2]) : lo32(acc[rp][2]);
                    float a3 = half ? hi32(acc[rp][3]) : lo32(acc[rp][3]);
                    float z0 = a0 + xrow[0]         + bb[0];   // i
                    float z1 = a1 + xrow[UNITS]     + bb[1];   // f
                    float z2 = a2 + xrow[2 * UNITS] + bb[2];   // g
                    float z3 = a3 + xrow[3 * UNITS] + bb[3];   // o
                    float ig = sigm(z0), fg = sigm(z1), gg = tanh_f(z2), og = sigm(z3);
                    int   ci = bg * UNITS + u;
                    float cn = fg * g_c[ci] + ig * gg;
                    g_c[ci] = cn;
                    g_h[ci] = og * tanh_f(cn);
                }
            }
        }

        // ---- transpose new h back into smem for next step ----
        __syncthreads();
        #pragma unroll
        for (int j = 0; j < (BM * UNITS) / NTHREADS; ++j) {   // 64 elems/thread
            int idx = tid + NTHREADS * j;
            int r   = idx >> 8;           // 0..127
            int u2  = idx & 255;
            hT[u2 * HT_STRIDE + r] = g_h[(b0 + r) * UNITS + u2];
        }
        // next chunk's leading __syncthreads orders these writes before reads
    }
    __syncthreads();

    // ================= output: logits + softmax =================
    const int lane = tid & 31;       // covers v = 4*lane .. 4*lane+3
    const int wrp  = tid >> 5;       // warp -> rows [8*wrp, 8*wrp+8)
    float accv[8][4];
    #pragma unroll
    for (int rr = 0; rr < 8; ++rr)
        #pragma unroll
        for (int c = 0; c < 4; ++c) accv[rr][c] = 0.0f;

    for (int p = 0; p < 2; ++p) {            // W_out in two 128-row halves
        __syncthreads();
        #pragma unroll
        for (int j = 0; j < 8; ++j) {
            int q  = tid + NTHREADS * j;
            int uu = q >> 5;
            int vq = (q & 31) << 2;
            *reinterpret_cast<float4*>(&Wsh[uu * 128 + vq]) =
                *reinterpret_cast<const float4*>(W_out + (p * 128 + uu) * VOCAB + vq);
        }
        __syncthreads();
        for (int uu = 0; uu < 128; ++uu) {
            float4 wv = *reinterpret_cast<const float4*>(&Wsh[uu * 128 + (lane << 2)]);
            const float* hcol = &hT[(p * 128 + uu) * HT_STRIDE + (wrp << 3)];
            #pragma unroll
            for (int rr = 0; rr < 8; ++rr) {
                float hv = hcol[rr];     // broadcast within warp
                accv[rr][0] += hv * wv.x;
                accv[rr][1] += hv * wv.y;
                accv[rr][2] += hv * wv.z;
                accv[rr][3] += hv * wv.w;
            }
        }
    }

    float4 bo = *reinterpret_cast<const float4*>(b_out + (lane << 2));
    #pragma unroll
    for (int rr = 0; rr < 8; ++rr) {
        float l0 = accv[rr][0] + bo.x;
        float l1 = accv[rr][1] + bo.y;
        float l2 = accv[rr][2] + bo.z;
        float l3 = accv[rr][3] + bo.w;
        float m = fmaxf(fmaxf(l0, l1), fmaxf(l2, l3));
        #pragma unroll
        for (int s = 16; s > 0; s >>= 1) m = fmaxf(m, __shfl_xor_sync(0xffffffffu, m, s));
        float e0 = __expf(l0 - m), e1 = __expf(l1 - m);
        float e2 = __expf(l2 - m), e3 = __expf(l3 - m);
        float sum = e0 + e1 + e2 + e3;
        #pragma unroll
        for (int s = 16; s > 0; s >>= 1) sum += __shfl_xor_sync(0xffffffffu, sum, s);
        float inv = __fdividef(1.0f, sum);
        int r = (wrp << 3) + rr;
        float4 res = make_float4(e0 * inv, e1 * inv, e2 * inv, e3 * inv);
        *reinterpret_cast<float4*>(out + (b0 + r) * VOCAB + (lane << 2)) = res;
    }
}

extern "C" void kernel_launch(void* const* d_in, const int* in_sizes, int n_in,
                              void* d_out, int out_size)
{
    (void)in_sizes; (void)n_in; (void)out_size;
    const int*   inputs = (const int*)  d_in[0];
    const float* W_ih   = (const float*)d_in[1];
    const float* W_hh   = (const float*)d_in[2];
    const float* b      = (const float*)d_in[3];
    const float* W_out  = (const float*)d_in[4];
    const float* b_out  = (const float*)d_in[5];
    float* out = (float*)d_out;

    cudaFuncSetAttribute(lstm_persist_kernel,
                         cudaFuncAttributeMaxDynamicSharedMemorySize, SMEM_BYTES);
    lstm_persist_kernel<<<GRID, NTHREADS, SMEM_BYTES>>>(
        inputs, W_ih, W_hh, b, W_out, b_out, out);
}